// round 4
// baseline (speedup 1.0000x reference)
#include <cuda_runtime.h>
#include <cstdint>
#include <cstddef>

// Reverse LSTM: B=128, T=2048, H=512.  out[b,t,:] = h_t (consumes x[b, T-1-t]).
//
// Dual-batch-group persistent kernel: 128 CTAs = 2 sets x 64 col-groups.
// Each CTA owns 32 z-cols (8 h-cols x 4 gates, Wh slice 64KB SMEM) and serves
// TWO batch groups (A, B) of 32 rows each, alternating within a step so that
// each group's h-staging + barrier skew hides behind the other group's GEMM.

#define TT   2048
#define HID  512
#define PAD  34          // z exchange row pad (floats), keeps STS.64 aligned

__device__ float    g_Hbuf[2][4][HID * 32];   // [parity][bg][k*32 + b] k-major
__device__ unsigned g_cnt[4];

typedef unsigned long long u64;

__device__ __forceinline__ void ffma2(u64 &d, u64 a, u64 b) {
    asm volatile("fma.rn.f32x2 %0, %1, %2, %0;" : "+l"(d) : "l"(a), "l"(b));
}
__device__ __forceinline__ u64 pack2(float x) {
    u64 r; asm("mov.b64 %0, {%1, %1};" : "=l"(r) : "f"(x)); return r;
}
__device__ __forceinline__ void cp16(void* s, const void* g) {
    unsigned sa = (unsigned)__cvta_generic_to_shared(s);
    asm volatile("cp.async.cg.shared.global [%0], [%1], 16;" :: "r"(sa), "l"(g) : "memory");
}
__device__ __forceinline__ float lo32(u64 v) { return __uint_as_float((unsigned)(v & 0xffffffffull)); }
__device__ __forceinline__ float hi32(u64 v) { return __uint_as_float((unsigned)(v >> 32)); }

__global__ void lstm_init_kernel() {
    if (threadIdx.x < 4) g_cnt[threadIdx.x] = 0u;
}

extern __shared__ float sm[];

__global__ void __launch_bounds__(128, 1)
lstm_persistent_kernel(const float* __restrict__ x,
                       const float* __restrict__ Wi,
                       const float* __restrict__ Wh,
                       const float* __restrict__ bias,
                       float* __restrict__ out)
{
    // SMEM (floats):
    float* Wh_s = sm;            // [512][32]        65536 B
    float* hA_s = sm + 16384;    // [512][32]        65536 B (k-major, batch contiguous)
    float* hB_s = sm + 32768;    // [512][32]        65536 B
    float* z2   = sm + 49152;    // [2 kh][32 c][PAD] 8704 B
    float* xA_s = sm + 49152 + 2 * 32 * PAD;  // [32]
    float* xB_s = xA_s + 32;                  // [32]   total 51392 fl = 205568 B

    const int tid  = threadIdx.x;
    const int set  = blockIdx.x >> 6;    // 0..1
    const int cg   = blockIdx.x & 63;    // 0..63 -> h-cols cg*8..cg*8+7
    const int bgA  = set * 2;
    const int bgB  = set * 2 + 1;

    const int lane16 = tid & 15;         // col-pair (c0 = 2*lane16, c1 = c0+1)
    const int oct    = (tid >> 4) & 3;   // batch octet (8 batches)
    const int kh     = tid >> 6;         // k-half (0: k<256, 1: k>=256)

    const int gj = tid & 7;              // gate-phase h-col
    const int gb = tid >> 3;             // gate-phase batch row (0..15; +16 for inst 1)

    // ---- One-time: Wh slice, Wi/bias regs ----
    // Local col c = j*4 + g  <->  global z-col g*512 + cg*8 + j
    for (int idx = tid; idx < HID * 32; idx += 128) {
        int k = idx >> 5, c = idx & 31;
        int j = c >> 2, g = c & 3;
        Wh_s[idx] = Wh[(size_t)k * 2048 + g * 512 + cg * 8 + j];
    }
    float wi_r[4], bi_r[4];
    #pragma unroll
    for (int g = 0; g < 4; ++g) {
        wi_r[g] = Wi[g * 512 + cg * 8 + gj];
        bi_r[g] = bias[g * 512 + cg * 8 + gj];
    }
    __syncthreads();

    float cA[2] = {0.f, 0.f}, cB[2] = {0.f, 0.f};

    volatile unsigned* cbA = &g_cnt[bgA];
    volatile unsigned* cbB = &g_cnt[bgB];
    const size_t TH = (size_t)TT * HID;

    const float* hp_base_A = hA_s + oct * 8;
    const float* hp_base_B = hB_s + oct * 8;
    const float* wp_base   = Wh_s + lane16 * 2;
    const int    k0        = kh * 256;

    for (int t = 0; t < TT; ++t) {
        // ================= top: acquire B barrier, stage h_B =================
        if (t > 0) {
            if (tid == 0) {
                unsigned tgt = 64u * (unsigned)t;      // bar_B[t-1]
                while (*cbB < tgt) { }
            }
            __syncthreads();
            const float* srcB = &g_Hbuf[t & 1][bgB][0];
            #pragma unroll 8
            for (int i = tid; i < 4096; i += 128) cp16(hB_s + 4 * i, srcB + 4 * i);
            asm volatile("cp.async.commit_group;" ::: "memory");
        }
        // x for both groups (consumed after later syncs)
        if (tid < 32)
            xA_s[tid] = x[(size_t)(bgA * 32 + tid) * TT + (TT - 1 - t)];
        else if (tid < 64)
            xB_s[tid - 32] = x[(size_t)(bgB * 32 + (tid - 32)) * TT + (TT - 1 - t)];

        // ================= GEMM A =================
        u64 a00 = 0, a01 = 0, a02 = 0, a03 = 0;
        u64 a10 = 0, a11 = 0, a12 = 0, a13 = 0;
        if (t > 0) {
            asm volatile("cp.async.wait_group 1;" ::: "memory");  // h_A (issued last iter) done
            __syncthreads();
            #pragma unroll 8
            for (int kk = 0; kk < 256; ++kk) {
                int k = k0 + kk;
                ulonglong2 h0 = *(const ulonglong2*)(hp_base_A + k * 32);
                ulonglong2 h1 = *(const ulonglong2*)(hp_base_A + k * 32 + 4);
                float2 w = *(const float2*)(wp_base + k * 32);
                u64 W0 = pack2(w.x), W1 = pack2(w.y);
                ffma2(a00, h0.x, W0); ffma2(a01, h0.y, W0);
                ffma2(a02, h1.x, W0); ffma2(a03, h1.y, W0);
                ffma2(a10, h0.x, W1); ffma2(a11, h0.y, W1);
                ffma2(a12, h1.x, W1); ffma2(a13, h1.y, W1);
            }
        }
        // scatter z partials: z2[kh][c][b-pairs]
        {
            float* zp = z2 + kh * 32 * PAD;
            int c0 = lane16 * 2;
            float* q0 = zp + c0 * PAD + oct * 8;
            float* q1 = zp + (c0 + 1) * PAD + oct * 8;
            *(u64*)(q0 + 0) = a00; *(u64*)(q0 + 2) = a01;
            *(u64*)(q0 + 4) = a02; *(u64*)(q0 + 6) = a03;
            *(u64*)(q1 + 0) = a10; *(u64*)(q1 + 2) = a11;
            *(u64*)(q1 + 4) = a12; *(u64*)(q1 + 6) = a13;
        }
        __syncthreads();

        // ================= gates A =================
        {
            float* hnb = &g_Hbuf[(t + 1) & 1][bgA][0];
            #pragma unroll
            for (int inst = 0; inst < 2; ++inst) {
                int b = gb + inst * 16;
                float zg_[4];
                #pragma unroll
                for (int g = 0; g < 4; ++g) {
                    int c = gj * 4 + g;
                    zg_[g] = z2[c * PAD + b] + z2[32 * PAD + c * PAD + b];
                }
                float xr = xA_s[b];
                float vi = zg_[0] + xr * wi_r[0] + bi_r[0];
                float vf = zg_[1] + xr * wi_r[1] + bi_r[1];
                float vg = zg_[2] + xr * wi_r[2] + bi_r[2];
                float vo = zg_[3] + xr * wi_r[3] + bi_r[3];
                float ig = 1.0f / (1.0f + __expf(-vi));
                float fg = 1.0f / (1.0f + __expf(-vf));
                float eg = __expf(2.0f * vg);
                float gv = 1.0f - 2.0f / (eg + 1.0f);
                float og = 1.0f / (1.0f + __expf(-vo));
                float cn = fg * cA[inst] + ig * gv;
                cA[inst] = cn;
                float ec = __expf(2.0f * cn);
                float hr = og * (1.0f - 2.0f / (ec + 1.0f));
                out[(size_t)(bgA * 32 + b) * TH + (size_t)t * HID + cg * 8 + gj] = hr;
                hnb[(cg * 8 + gj) * 32 + b] = hr;
            }
        }
        __syncthreads();
        // arrive + acquire A barrier (skew hides behind GEMM B)
        if (tid == 0) {
            __threadfence();
            atomicAdd(&g_cnt[bgA], 1u);
            unsigned tgt = 64u * (unsigned)(t + 1);
            while (*cbA < tgt) { }
        }
        __syncthreads();
        // stage h_A for step t+1 (latency hidden behind GEMM B)
        {
            const float* srcA = &g_Hbuf[(t + 1) & 1][bgA][0];
            #pragma unroll 8
            for (int i = tid; i < 4096; i += 128) cp16(hA_s + 4 * i, srcA + 4 * i);
            asm volatile("cp.async.commit_group;" ::: "memory");
        }

        // ================= GEMM B =================
        u64 b00 = 0, b01 = 0, b02 = 0, b03 = 0;
        u64 b10 = 0, b11 = 0, b12 = 0, b13 = 0;
        if (t > 0) {
            asm volatile("cp.async.wait_group 1;" ::: "memory");  // h_B (issued at top) done
            __syncthreads();
            #pragma unroll 8
            for (int kk = 0; kk < 256; ++kk) {
                int k = k0 + kk;
                ulonglong2 h0 = *(const ulonglong2*)(hp_base_B + k * 32);
                ulonglong2 h1 = *(const ulonglong2*)(hp_base_B + k * 32 + 4);
                float2 w = *(const float2*)(wp_base + k * 32);
                u64 W0 = pack2(w.x), W1 = pack2(w.y);
                ffma2(b00, h0.x, W0); ffma2(b01, h0.y, W0);
                ffma2(b02, h1.x, W0); ffma2(b03, h1.y, W0);
                ffma2(b10, h0.x, W1); ffma2(b11, h0.y, W1);
                ffma2(b12, h1.x, W1); ffma2(b13, h1.y, W1);
            }
        } else {
            __syncthreads();   // keep z2 write/read ordering uniform at t=0
        }
        {
            float* zp = z2 + kh * 32 * PAD;
            int c0 = lane16 * 2;
            float* q0 = zp + c0 * PAD + oct * 8;
            float* q1 = zp + (c0 + 1) * PAD + oct * 8;
            *(u64*)(q0 + 0) = b00; *(u64*)(q0 + 2) = b01;
            *(u64*)(q0 + 4) = b02; *(u64*)(q0 + 6) = b03;
            *(u64*)(q1 + 0) = b10; *(u64*)(q1 + 2) = b11;
            *(u64*)(q1 + 4) = b12; *(u64*)(q1 + 6) = b13;
        }
        __syncthreads();

        // ================= gates B =================
        {
            float* hnb = &g_Hbuf[(t + 1) & 1][bgB][0];
            #pragma unroll
            for (int inst = 0; inst < 2; ++inst) {
                int b = gb + inst * 16;
                float zg_[4];
                #pragma unroll
                for (int g = 0; g < 4; ++g) {
                    int c = gj * 4 + g;
                    zg_[g] = z2[c * PAD + b] + z2[32 * PAD + c * PAD + b];
                }
                float xr = xB_s[b];
                float vi = zg_[0] + xr * wi_r[0] + bi_r[0];
                float vf = zg_[1] + xr * wi_r[1] + bi_r[1];
                float vg = zg_[2] + xr * wi_r[2] + bi_r[2];
                float vo = zg_[3] + xr * wi_r[3] + bi_r[3];
                float ig = 1.0f / (1.0f + __expf(-vi));
                float fg = 1.0f / (1.0f + __expf(-vf));
                float eg = __expf(2.0f * vg);
                float gv = 1.0f - 2.0f / (eg + 1.0f);
                float og = 1.0f / (1.0f + __expf(-vo));
                float cn = fg * cB[inst] + ig * gv;
                cB[inst] = cn;
                float ec = __expf(2.0f * cn);
                float hr = og * (1.0f - 2.0f / (ec + 1.0f));
                out[(size_t)(bgB * 32 + b) * TH + (size_t)t * HID + cg * 8 + gj] = hr;
                hnb[(cg * 8 + gj) * 32 + b] = hr;
            }
        }
        __syncthreads();
        if (tid == 0) {
            __threadfence();
            atomicAdd(&g_cnt[bgB], 1u);   // bar_B[t]; acquired at next iter top
        }
        __syncthreads();
    }
}

extern "C" void kernel_launch(void* const* d_in, const int* in_sizes, int n_in,
                              void* d_out, int out_size)
{
    // inputs: [0]=s (unused), [1]=x (128*2048), [2]=Wi (2048), [3]=Wh (512*2048), [4]=b (2048)
    const float* x    = (const float*)d_in[1];
    const float* Wi   = (const float*)d_in[2];
    const float* Wh   = (const float*)d_in[3];
    const float* bias = (const float*)d_in[4];
    float* out = (float*)d_out;

    size_t smem = (size_t)(49152 + 2 * 32 * PAD + 64) * sizeof(float);  // 205824 B
    cudaFuncSetAttribute(lstm_persistent_kernel,
                         cudaFuncAttributeMaxDynamicSharedMemorySize, (int)smem);

    lstm_init_kernel<<<1, 32>>>();
    lstm_persistent_kernel<<<128, 128, smem>>>(x, Wi, Wh, bias, out);
}

// round 5
// speedup vs baseline: 1.0663x; 1.0663x over previous
#include <cuda_runtime.h>
#include <cstdint>
#include <cstddef>

// Reverse LSTM: B=128, T=2048, H=512.  out[b,t,:] = h_t (consumes x[b, T-1-t]).
//
// Persistent kernel, R2 topology: 128 CTAs = 4 batch-groups (bg, 32 rows) x 32
// col-groups (cg, 16 h-cols = 64 z-cols). Wh slice (512x64 f32 = 128KB) in SMEM.
// New in R4:
//  - in-register gates: thread owns (1 h-col, 4 gates, 4 batches); z never hits smem
//  - k-chunked producer flags: stage h in 4x(128k) chunks via cp.async.cg, each
//    guarded by 8 per-CTA release flags; staging+skew hides behind GEMM chunks.

#define TT   2048
#define HID  512
#define FPAD 32              // flag padding (uints) -> 128B per flag

__device__ float    g_Hbuf[2][4][HID * 32];    // [parity][bg][k*32 + b]  k-major
__device__ unsigned g_flag[4][32][FPAD];       // [bg][cg][0], padded

typedef unsigned long long u64;

__device__ __forceinline__ void ffma2(u64 &d, u64 a, u64 b) {
    asm volatile("fma.rn.f32x2 %0, %1, %2, %0;" : "+l"(d) : "l"(a), "l"(b));
}
__device__ __forceinline__ u64 pack2(float x) {
    u64 r; asm("mov.b64 %0, {%1, %1};" : "=l"(r) : "f"(x)); return r;
}
__device__ __forceinline__ float lo32(u64 v) { return __uint_as_float((unsigned)v); }
__device__ __forceinline__ float hi32(u64 v) { return __uint_as_float((unsigned)(v >> 32)); }
__device__ __forceinline__ void cp16(void* s, const void* g) {
    unsigned sa = (unsigned)__cvta_generic_to_shared(s);
    asm volatile("cp.async.cg.shared.global [%0], [%1], 16;" :: "r"(sa), "l"(g) : "memory");
}
__device__ __forceinline__ void poll_flag(const unsigned* f, unsigned tgt) {
    unsigned v;
    do {
        asm volatile("ld.acquire.gpu.global.u32 %0, [%1];" : "=r"(v) : "l"(f));
    } while (v < tgt);
}

__global__ void lstm_init_kernel() {
    int i = threadIdx.x;                // 128 = 4*32 flags
    g_flag[i >> 5][i & 31][0] = 0u;
}

extern __shared__ float sm[];

__global__ void __launch_bounds__(128, 1)
lstm_persistent_kernel(const float* __restrict__ x,
                       const float* __restrict__ Wi,
                       const float* __restrict__ Wh,
                       const float* __restrict__ bias,
                       float* __restrict__ out)
{
    // SMEM (floats): Wh_s [512][64] = 131072B, h_s [512][32] = 65536B, x_s[32]
    float* Wh_s = sm;              // layout: Wh_s[k*64 + j*4 + g]
    float* h_s  = sm + 32768;      // layout: h_s[k*32 + b]
    float* x_s  = sm + 49152;

    const int tid = threadIdx.x;
    const int bg  = blockIdx.x >> 5;     // 0..3
    const int cg  = blockIdx.x & 31;     // 0..31 -> h-cols cg*16..cg*16+15
    const int j   = tid & 15;            // local h-col
    const int bq  = tid >> 4;            // batch quad (0..7) -> batches bq*4..bq*4+3

    // ---- One-time: Wh slice (col c = j*4+g <-> global g*512 + cg*16 + j) ----
    for (int idx = tid; idx < HID * 64; idx += 128) {
        int k = idx >> 6, c = idx & 63;
        int jj = c >> 2, g = c & 3;
        Wh_s[idx] = Wh[(size_t)k * 2048 + g * 512 + cg * 16 + jj];
    }
    float wi_r[4], bi_r[4];
    #pragma unroll
    for (int g = 0; g < 4; ++g) {
        wi_r[g] = Wi[g * 512 + cg * 16 + j];
        bi_r[g] = bias[g * 512 + cg * 16 + j];
    }
    __syncthreads();

    float cst[4] = {0.f, 0.f, 0.f, 0.f};
    const size_t TH = (size_t)TT * HID;
    const int fidx = tid & 7;            // which producer flag this thread polls

    for (int t = 0; t < TT; ++t) {
        // x for this step (read by gates after the bars below)
        if (tid < 32)
            x_s[tid] = x[(size_t)(bg * 32 + tid) * TT + (TT - 1 - t)];

        u64 a00 = 0, a01 = 0, a10 = 0, a11 = 0;
        u64 a20 = 0, a21 = 0, a30 = 0, a31 = 0;

        if (t > 0) {
            const float* Hsrc = &g_Hbuf[t & 1][bg][0];
            const unsigned tgt = (unsigned)t;

            // ---- stage chunk Q: poll its producer flag, then cp.async 16KB ----
            #define STAGE(Q) do {                                               \
                poll_flag(&g_flag[bg][(Q) * 8 + fidx][0], tgt);                  \
                const float* src = Hsrc + (Q) * 4096;                            \
                float*       dst = h_s  + (Q) * 4096;                            \
                _Pragma("unroll")                                                \
                for (int u = 0; u < 8; ++u)                                      \
                    cp16(dst + 4 * (tid + 128 * u), src + 4 * (tid + 128 * u));  \
                asm volatile("cp.async.commit_group;" ::: "memory");             \
            } while (0)

            #define WAITG(N) do {                                               \
                asm volatile("cp.async.wait_group %0;" :: "n"(N) : "memory");    \
                __syncthreads();                                                 \
            } while (0)

            // ---- GEMM over chunk Q (128 k): 8 FFMA2 per k, in-register z ----
            #define GEMM_CHUNK(Q) do {                                           \
                const float* hp = h_s  + (Q) * 4096 + bq * 4;                     \
                const float* wp = Wh_s + (Q) * 8192 + j * 4;                      \
                _Pragma("unroll 8")                                               \
                for (int kk = 0; kk < 128; ++kk) {                                \
                    ulonglong2 hv = *(const ulonglong2*)(hp + kk * 32);           \
                    float4     w4 = *(const float4*)    (wp + kk * 64);           \
                    u64 w0 = pack2(w4.x), w1 = pack2(w4.y);                       \
                    u64 w2 = pack2(w4.z), w3 = pack2(w4.w);                       \
                    ffma2(a00, hv.x, w0); ffma2(a01, hv.y, w0);                   \
                    ffma2(a10, hv.x, w1); ffma2(a11, hv.y, w1);                   \
                    ffma2(a20, hv.x, w2); ffma2(a21, hv.y, w2);                   \
                    ffma2(a30, hv.x, w3); ffma2(a31, hv.y, w3);                   \
                }                                                                 \
            } while (0)

            STAGE(0);
            STAGE(1);
            WAITG(1); GEMM_CHUNK(0);
            STAGE(2);
            WAITG(1); GEMM_CHUNK(1);
            STAGE(3);
            WAITG(1); GEMM_CHUNK(2);
            WAITG(0); GEMM_CHUNK(3);

            #undef STAGE
            #undef WAITG
            #undef GEMM_CHUNK
        } else {
            __syncthreads();   // x_s visibility at t=0
        }

        // ---- gates (in-register z), state update, publish ----
        {
            float zi_[4] = { lo32(a00), hi32(a00), lo32(a01), hi32(a01) };
            float zf_[4] = { lo32(a10), hi32(a10), lo32(a11), hi32(a11) };
            float zg_[4] = { lo32(a20), hi32(a20), lo32(a21), hi32(a21) };
            float zo_[4] = { lo32(a30), hi32(a30), lo32(a31), hi32(a31) };
            float4 xv = *(const float4*)(x_s + bq * 4);
            float xv_[4] = { xv.x, xv.y, xv.z, xv.w };
            float hv[4];

            size_t obase = (size_t)(bg * 32 + bq * 4) * TH
                         + (size_t)t * HID + cg * 16 + j;
            #pragma unroll
            for (int r = 0; r < 4; ++r) {
                float xr = xv_[r];
                float vi = zi_[r] + xr * wi_r[0] + bi_r[0];
                float vf = zf_[r] + xr * wi_r[1] + bi_r[1];
                float vg = zg_[r] + xr * wi_r[2] + bi_r[2];
                float vo = zo_[r] + xr * wi_r[3] + bi_r[3];
                float ig = 1.0f / (1.0f + __expf(-vi));
                float fg = 1.0f / (1.0f + __expf(-vf));
                float eg = __expf(2.0f * vg);
                float gv = 1.0f - 2.0f / (eg + 1.0f);         // tanh(vg)
                float og = 1.0f / (1.0f + __expf(-vo));
                float cn = fg * cst[r] + ig * gv;
                cst[r] = cn;
                float ec = __expf(2.0f * cn);
                float hr = og * (1.0f - 2.0f / (ec + 1.0f));  // o * tanh(c)
                hv[r] = hr;
                out[obase + (size_t)r * TH] = hr;
            }
            // k-major publish for next step's staged GEMM loads
            float* hn = &g_Hbuf[(t + 1) & 1][bg][(cg * 16 + j) * 32 + bq * 4];
            *(float4*)hn = make_float4(hv[0], hv[1], hv[2], hv[3]);
        }

        // ---- release: all h written -> fence -> bump this CTA's flag ----
        __syncthreads();
        if (tid == 0) {
            __threadfence();
            asm volatile("st.release.gpu.global.u32 [%0], %1;"
                         :: "l"(&g_flag[bg][cg][0]), "r"((unsigned)(t + 1))
                         : "memory");
        }
    }
}

extern "C" void kernel_launch(void* const* d_in, const int* in_sizes, int n_in,
                              void* d_out, int out_size)
{
    // inputs: [0]=s (unused), [1]=x (128*2048), [2]=Wi (2048), [3]=Wh (512*2048), [4]=b (2048)
    const float* x    = (const float*)d_in[1];
    const float* Wi   = (const float*)d_in[2];
    const float* Wh   = (const float*)d_in[3];
    const float* bias = (const float*)d_in[4];
    float* out = (float*)d_out;

    size_t smem = (size_t)(49152 + 64) * sizeof(float);   // 196864 B
    cudaFuncSetAttribute(lstm_persistent_kernel,
                         cudaFuncAttributeMaxDynamicSharedMemorySize, (int)smem);

    lstm_init_kernel<<<1, 128>>>();
    lstm_persistent_kernel<<<128, 128, smem>>>(x, Wi, Wh, bias, out);
}

// round 6
// speedup vs baseline: 1.1961x; 1.1218x over previous
#include <cuda_runtime.h>
#include <cstdint>
#include <cstddef>

// Reverse LSTM: B=128, T=2048, H=512.  out[b,t,:] = h_t (consumes x[b, T-1-t]).
//
// Persistent kernel: 128 CTAs = 4 batch-groups (bg, 32 rows) x 32 col-groups
// (cg, 16 h-cols = 64 z-cols). Wh slice (512x64 f32 = 128KB) SMEM-resident.
// R5: h staged per step with TWO cp.async.bulk (TMA) ops of 32KB instead of
// 4096 cp.async.cg 16B ops (which cost ~8192 cyc of LSU issue per step in
// R2/R4 and were the hidden serial tail). mbarrier complete_tx completion;
// in-register z (no z smem round-trip); per-CTA release flags.

#define TT   2048
#define HID  512
#define FPAD 32              // flag padding (uints) -> 128B per flag

__device__ float    g_Hbuf[2][4][HID * 32];    // [parity][bg][k*32 + b]  k-major
__device__ unsigned g_flag[4][32][FPAD];       // [bg][cg][0], padded

typedef unsigned long long u64;

__device__ __forceinline__ void ffma2(u64 &d, u64 a, u64 b) {
    asm volatile("fma.rn.f32x2 %0, %1, %2, %0;" : "+l"(d) : "l"(a), "l"(b));
}
__device__ __forceinline__ u64 pack2(float x) {
    u64 r; asm("mov.b64 %0, {%1, %1};" : "=l"(r) : "f"(x)); return r;
}
__device__ __forceinline__ float lo32(u64 v) { return __uint_as_float((unsigned)v); }
__device__ __forceinline__ float hi32(u64 v) { return __uint_as_float((unsigned)(v >> 32)); }

__device__ __forceinline__ void poll_flag(const unsigned* f, unsigned tgt) {
    unsigned v;
    do {
        asm volatile("ld.acquire.gpu.global.u32 %0, [%1];" : "=r"(v) : "l"(f));
    } while (v < tgt);
}
__device__ __forceinline__ void bulk_g2s(unsigned dst_smem, const void* src,
                                         unsigned bytes, unsigned mbar) {
    asm volatile(
        "cp.async.bulk.shared::cluster.global.mbarrier::complete_tx::bytes "
        "[%0], [%1], %2, [%3];"
        :: "r"(dst_smem), "l"(src), "r"(bytes), "r"(mbar) : "memory");
}
__device__ __forceinline__ void mbar_init(unsigned mbar, unsigned cnt) {
    asm volatile("mbarrier.init.shared.b64 [%0], %1;" :: "r"(mbar), "r"(cnt) : "memory");
}
__device__ __forceinline__ void mbar_expect_tx(unsigned mbar, unsigned bytes) {
    asm volatile("mbarrier.arrive.expect_tx.shared.b64 _, [%0], %1;"
                 :: "r"(mbar), "r"(bytes) : "memory");
}
__device__ __forceinline__ void mbar_wait(unsigned mbar, unsigned parity) {
    unsigned done;
    asm volatile(
        "{\n\t.reg .pred p;\n\t"
        "mbarrier.try_wait.parity.acquire.cta.shared::cta.b64 p, [%1], %2;\n\t"
        "selp.b32 %0, 1, 0, p;\n\t}"
        : "=r"(done) : "r"(mbar), "r"(parity) : "memory");
    if (!done) {
        asm volatile(
            "{\n\t.reg .pred P1;\n\t"
            "WL_%=:\n\t"
            "mbarrier.try_wait.parity.acquire.cta.shared::cta.b64 P1, [%0], %1, 0x989680;\n\t"
            "@P1 bra.uni WD_%=;\n\t"
            "bra.uni WL_%=;\n\t"
            "WD_%=:\n\t}"
            :: "r"(mbar), "r"(parity) : "memory");
    }
}

__global__ void lstm_init_kernel() {
    int i = threadIdx.x;                // 128 = 4*32 flags
    g_flag[i >> 5][i & 31][0] = 0u;
}

extern __shared__ float sm[];

__global__ void __launch_bounds__(128, 1)
lstm_persistent_kernel(const float* __restrict__ x,
                       const float* __restrict__ Wi,
                       const float* __restrict__ Wh,
                       const float* __restrict__ bias,
                       float* __restrict__ out)
{
    // SMEM (floats): Wh_s[512][64]=131072B @0, h_s[512][32]=65536B @32768,
    // x_s[32] @49152, mbar[2] (u64) @49184 (16B-aligned region)
    float* Wh_s = sm;                   // Wh_s[k*64 + j*4 + g]
    float* h_s  = sm + 32768;           // h_s[k*32 + b]
    float* x_s  = sm + 49152;

    const int tid = threadIdx.x;
    const int bg  = blockIdx.x >> 5;     // 0..3
    const int cg  = blockIdx.x & 31;     // 0..31 -> h-cols cg*16..cg*16+15
    const int j   = tid & 15;            // local h-col
    const int bq  = tid >> 4;            // batch quad (0..7)

    const unsigned smem_base = (unsigned)__cvta_generic_to_shared(sm);
    const unsigned h_smem    = smem_base + 32768u * 4u;
    const unsigned mbar0     = smem_base + 49184u * 4u;
    const unsigned mbar1     = mbar0 + 8u;

    if (tid == 0) { mbar_init(mbar0, 1); mbar_init(mbar1, 1); }

    // ---- One-time: Wh slice (local col c = j*4+g <-> global g*512 + cg*16 + j) ----
    for (int idx = tid; idx < HID * 64; idx += 128) {
        int k = idx >> 6, c = idx & 63;
        int jj = c >> 2, g = c & 3;
        Wh_s[idx] = Wh[(size_t)k * 2048 + g * 512 + cg * 16 + jj];
    }
    float wi_r[4], bi_r[4];
    #pragma unroll
    for (int g = 0; g < 4; ++g) {
        wi_r[g] = Wi[g * 512 + cg * 16 + j];
        bi_r[g] = bias[g * 512 + cg * 16 + j];
    }
    __syncthreads();

    float cst[4] = {0.f, 0.f, 0.f, 0.f};
    const size_t TH = (size_t)TT * HID;

    for (int t = 0; t < TT; ++t) {
        // x for this step (warp 1; consumed after the syncthreads below)
        if (tid >= 32 && tid < 64)
            x_s[tid - 32] = x[(size_t)(bg * 32 + (tid - 32)) * TT + (TT - 1 - t)];

        const unsigned ph = (unsigned)((t + 1) & 1);   // mbar parity for step t (t>=1)

        if (t > 0) {
            const float* Hsrc = &g_Hbuf[t & 1][bg][0];
            const unsigned tgt = (unsigned)t;
            // warp 0: lanes 0-15 gate half0 (k 0..255, producers cg 0..15),
            //         lanes 16-31 gate half1 (k 256..511, producers cg 16..31)
            if (tid < 16) {
                poll_flag(&g_flag[bg][tid][0], tgt);
                __syncwarp(0x0000FFFFu);
                if (tid == 0) {
                    mbar_expect_tx(mbar0, 32768u);
                    bulk_g2s(h_smem, Hsrc, 32768u, mbar0);
                }
            } else if (tid < 32) {
                poll_flag(&g_flag[bg][tid][0], tgt);
                __syncwarp(0xFFFF0000u);
                if (tid == 16) {
                    mbar_expect_tx(mbar1, 32768u);
                    bulk_g2s(h_smem + 32768u, Hsrc + 8192, 32768u, mbar1);
                }
            }
            mbar_wait(mbar0, ph);
        }
        __syncthreads();   // h half0 + x_s visible to all

        u64 a00 = 0, a01 = 0, a10 = 0, a11 = 0;
        u64 a20 = 0, a21 = 0, a30 = 0, a31 = 0;

        if (t > 0) {
            // ---- GEMM half Q (256 k): in-register z, 8 FFMA2/k ----
            #define GEMM_HALF(Q) do {                                             \
                const float* hp = h_s  + (Q) * 8192  + bq * 4;                     \
                const float* wp = Wh_s + (Q) * 16384 + j * 4;                      \
                _Pragma("unroll 8")                                                \
                for (int kk = 0; kk < 256; ++kk) {                                 \
                    ulonglong2 hv = *(const ulonglong2*)(hp + kk * 32);            \
                    float4     w4 = *(const float4*)    (wp + kk * 64);            \
                    u64 w0 = pack2(w4.x), w1 = pack2(w4.y);                        \
                    u64 w2 = pack2(w4.z), w3 = pack2(w4.w);                        \
                    ffma2(a00, hv.x, w0); ffma2(a01, hv.y, w0);                    \
                    ffma2(a10, hv.x, w1); ffma2(a11, hv.y, w1);                    \
                    ffma2(a20, hv.x, w2); ffma2(a21, hv.y, w2);                    \
                    ffma2(a30, hv.x, w3); ffma2(a31, hv.y, w3);                    \
                }                                                                  \
            } while (0)

            GEMM_HALF(0);
            mbar_wait(mbar1, ph);
            GEMM_HALF(1);
            #undef GEMM_HALF
        }

        // ---- gates (in-register z), state update, publish ----
        {
            float zi_[4] = { lo32(a00), hi32(a00), lo32(a01), hi32(a01) };
            float zf_[4] = { lo32(a10), hi32(a10), lo32(a11), hi32(a11) };
            float zg_[4] = { lo32(a20), hi32(a20), lo32(a21), hi32(a21) };
            float zo_[4] = { lo32(a30), hi32(a30), lo32(a31), hi32(a31) };
            float4 xv = *(const float4*)(x_s + bq * 4);
            float xv_[4] = { xv.x, xv.y, xv.z, xv.w };
            float hv[4];

            size_t obase = (size_t)(bg * 32 + bq * 4) * TH
                         + (size_t)t * HID + cg * 16 + j;
            #pragma unroll
            for (int r = 0; r < 4; ++r) {
                float xr = xv_[r];
                float vi = zi_[r] + xr * wi_r[0] + bi_r[0];
                float vf = zf_[r] + xr * wi_r[1] + bi_r[1];
                float vg = zg_[r] + xr * wi_r[2] + bi_r[2];
                float vo = zo_[r] + xr * wi_r[3] + bi_r[3];
                float ig = 1.0f / (1.0f + __expf(-vi));
                float fg = 1.0f / (1.0f + __expf(-vf));
                float eg = __expf(2.0f * vg);
                float gv = 1.0f - 2.0f / (eg + 1.0f);         // tanh(vg)
                float og = 1.0f / (1.0f + __expf(-vo));
                float cn = fg * cst[r] + ig * gv;
                cst[r] = cn;
                float ec = __expf(2.0f * cn);
                float hr = og * (1.0f - 2.0f / (ec + 1.0f));  // o * tanh(c)
                hv[r] = hr;
                out[obase + (size_t)r * TH] = hr;
            }
            // k-major publish for next step's bulk-staged GEMM loads
            float* hn = &g_Hbuf[(t + 1) & 1][bg][(cg * 16 + j) * 32 + bq * 4];
            *(float4*)hn = make_float4(hv[0], hv[1], hv[2], hv[3]);
        }

        // ---- release: all h published -> fence -> bump this CTA's flag ----
        __syncthreads();
        if (tid == 0) {
            __threadfence();
            asm volatile("st.release.gpu.global.u32 [%0], %1;"
                         :: "l"(&g_flag[bg][cg][0]), "r"((unsigned)(t + 1))
                         : "memory");
        }
    }
}

extern "C" void kernel_launch(void* const* d_in, const int* in_sizes, int n_in,
                              void* d_out, int out_size)
{
    // inputs: [0]=s (unused), [1]=x (128*2048), [2]=Wi (2048), [3]=Wh (512*2048), [4]=b (2048)
    const float* x    = (const float*)d_in[1];
    const float* Wi   = (const float*)d_in[2];
    const float* Wh   = (const float*)d_in[3];
    const float* bias = (const float*)d_in[4];
    float* out = (float*)d_out;

    size_t smem = (size_t)(49184 + 8) * sizeof(float);   // 196768 B
    cudaFuncSetAttribute(lstm_persistent_kernel,
                         cudaFuncAttributeMaxDynamicSharedMemorySize, (int)smem);

    lstm_init_kernel<<<1, 128>>>();
    lstm_persistent_kernel<<<128, 128, smem>>>(x, Wi, Wh, bias, out);
}